// round 10
// baseline (speedup 1.0000x reference)
#include <cuda_runtime.h>
#include <cuda_bf16.h>
#include <math.h>
#include <cstdint>

#define BATCH  4096
#define NIN    32
#define NHID   128
#define NOUT   30000
#define NCLUST 10000
#define BN_EPS 1e-3f

#define NCC      20000
#define NCC_PAD  20480
#define NBLK     313
#define CTAX     40

// ---- scratch ----
__device__ float g_h[BATCH * NHID];
__device__ float g_sum[NHID];
__device__ float g_sumsq[NHID];
__device__ float g_scale[NHID];
__device__ float g_shift[NHID];
__device__ __nv_bfloat16 g_Ah[BATCH * NHID];
__device__ __nv_bfloat16 g_Al[BATCH * NHID];
__device__ __nv_bfloat16 g_Bh[NCC_PAD * NHID];
__device__ __nv_bfloat16 g_Bl[NCC_PAD * NHID];
__device__ float2 g_b2p[10240];

// ---- MUFU-free exp / rcp ----------------------------------------------------
__device__ __forceinline__ float fexp(float x) {
    float t  = x * 1.4426950408889634f;
    float rf = t + 12582912.0f;
    int   ri = __float_as_int(rf) - 0x4B400000;
    float f  = t - (rf - 12582912.0f);
    float p = 1.5404000e-4f;
    p = fmaf(p, f, 1.3333558e-3f);
    p = fmaf(p, f, 9.6181291e-3f);
    p = fmaf(p, f, 5.5504109e-2f);
    p = fmaf(p, f, 2.4022651e-1f);
    p = fmaf(p, f, 6.9314718e-1f);
    p = fmaf(p, f, 1.0f);
    return __int_as_float(__float_as_int(p) + (ri << 23));
}
__device__ __forceinline__ float frcp(float d) {
    float r = __int_as_float(0x7EF127EAu - __float_as_int(d));
    #pragma unroll
    for (int i = 0; i < 3; i++) {
        float e = fmaf(-d, r, 1.0f);
        r = fmaf(r, e, r);
    }
    return r;
}

__device__ __forceinline__ uint32_t smem_u32(const void* p) {
    uint32_t a;
    asm("{ .reg .u64 t; cvta.to.shared.u64 t, %1; cvt.u32.u64 %0, t; }"
        : "=r"(a) : "l"(p));
    return a;
}
__device__ __forceinline__ void cp16(uint32_t dst, const void* src) {
    asm volatile("cp.async.cg.shared.global [%0], [%1], 16;"
                 :: "r"(dst), "l"(src));
}
__device__ __forceinline__ void cp_commit() {
    asm volatile("cp.async.commit_group;");
}
__device__ __forceinline__ void cp_wait0() {
    asm volatile("cp.async.wait_group 0;");
}
__device__ __forceinline__ void ldsm_x4(uint32_t& r0, uint32_t& r1,
                                        uint32_t& r2, uint32_t& r3, uint32_t a) {
    asm volatile("ldmatrix.sync.aligned.m8n8.x4.shared.b16 {%0,%1,%2,%3}, [%4];"
                 : "=r"(r0), "=r"(r1), "=r"(r2), "=r"(r3) : "r"(a));
}
__device__ __forceinline__ void mma16816(float* c, const uint32_t* a,
                                         const uint32_t* b) {
    asm volatile("mma.sync.aligned.m16n8k16.row.col.f32.bf16.bf16.f32 "
                 "{%0,%1,%2,%3}, {%4,%5,%6,%7}, {%8,%9}, {%0,%1,%2,%3};"
                 : "+f"(c[0]), "+f"(c[1]), "+f"(c[2]), "+f"(c[3])
                 : "r"(a[0]), "r"(a[1]), "r"(a[2]), "r"(a[3]),
                   "r"(b[0]), "r"(b[1]));
}

// ---------------------------------------------------------------------------
__global__ void k_init() {
    int i = threadIdx.x;
    if (i < NHID) { g_sum[i] = 0.0f; g_sumsq[i] = 0.0f; }
}

__global__ void k_h(const float* __restrict__ z,
                    const float* __restrict__ W1,
                    const float* __restrict__ b1) {
    __shared__ float zs[128][33];
    __shared__ float ws[128][33];
    __shared__ float ps[2][128];
    __shared__ float psq[2][128];

    const int tid   = threadIdx.x;
    const int rbase = blockIdx.x * 128;

    for (int idx = tid; idx < 128 * NIN; idx += 256) {
        int r = idx >> 5, k = idx & 31;
        zs[r][k] = z[(rbase + r) * NIN + k];
        ws[r][k] = W1[idx];
    }
    __syncthreads();

    const int col = tid & 127;
    const int rh  = tid >> 7;
    const float bb = b1[col];
    float ls = 0.0f, lsq = 0.0f;

    for (int r = rh * 64; r < rh * 64 + 64; r++) {
        float acc = bb;
        #pragma unroll
        for (int k = 0; k < NIN; k++)
            acc = fmaf(zs[r][k], ws[col][k], acc);
        g_h[(rbase + r) * NHID + col] = acc;
        ls += acc;
        lsq = fmaf(acc, acc, lsq);
    }
    ps[rh][col]  = ls;
    psq[rh][col] = lsq;
    __syncthreads();
    if (tid < 128) {
        atomicAdd(&g_sum[tid],   ps[0][tid]  + ps[1][tid]);
        atomicAdd(&g_sumsq[tid], psq[0][tid] + psq[1][tid]);
    }
}

__global__ void k_bn(const float* __restrict__ gamma,
                     const float* __restrict__ beta) {
    int c = threadIdx.x;
    if (c >= NHID) return;
    const float inv_b = 1.0f / (float)BATCH;
    float mu   = g_sum[c] * inv_b;
    float var  = g_sumsq[c] * inv_b - mu * mu;
    float rstd = rsqrtf(var + BN_EPS);
    float sc   = gamma[c] * rstd;
    g_scale[c] = sc;
    g_shift[c] = beta[c] - mu * sc;
}

__global__ void k_split_h() {
    const int idx = blockIdx.x * 256 + threadIdx.x;
    if (idx >= BATCH * NHID) return;
    const int k = idx & 127;
    float v = fmaxf(fmaf(g_h[idx], g_scale[k], g_shift[k]), 0.0f);
    __nv_bfloat16 hi = __float2bfloat16_rn(v);
    g_Ah[idx] = hi;
    g_Al[idx] = __float2bfloat16_rn(v - __bfloat162float(hi));
}

__global__ void k_split_w(const float* __restrict__ W2,
                          const float* __restrict__ b2) {
    const int idx = blockIdx.x * 256 + threadIdx.x;
    if (idx < 10240) {
        float2 bp = make_float2(0.0f, 0.0f);
        if (idx < NCLUST)
            bp = make_float2(b2[3 * idx + 1], b2[3 * idx + 2]);
        g_b2p[idx] = bp;
    }
    if (idx >= NCC_PAD * NHID) return;
    const int cc = idx >> 7;
    const int k  = idx & 127;
    float w = 0.0f;
    if (cc < NCC) {
        const int c = cc >> 1, j = cc & 1;
        w = W2[(size_t)(3 * c + 1 + j) * NHID + k];
    }
    __nv_bfloat16 hi = __float2bfloat16_rn(w);
    g_Bh[idx] = hi;
    g_Bl[idx] = __float2bfloat16_rn(w - __bfloat162float(hi));
}

// ---------------------------------------------------------------------------
// k_gemm: 64x64 tile, occupancy-3, cp.async staging, mma.sync, staged output.
// 8 warps in 2x4 grid (warp tile 32x16). A resident; B re-staged per block.
// ---------------------------------------------------------------------------
#define LDA 136
#define LDCB 100

#define OFF_AH 0
#define OFF_AL 17408
#define OFF_BH 34816
#define OFF_BL 52224
#define SMEM_DYN 69632          // Cbuf [64][100] f32 = 25600 overlays B region

extern "C" __global__ void __launch_bounds__(256, 3)
k_gemm(float* __restrict__ out) {
    extern __shared__ char sm[];
    float* Cbuf = (float*)(sm + OFF_BH);

    const int tid   = threadIdx.x;
    const int wid   = tid >> 5;
    const int lid   = tid & 31;
    const int rbase = blockIdx.y * 64;

    const uint32_t smB = smem_u32(sm);

    // thread's staging slot: 8 quad-copies per array; row = i>>4 (64 rows x 16 quads)
    const int s_row = tid >> 2;            // 0..63
    const int s_q   = tid & 3;             // 0..3 (x4 quads each)

    // --- prologue: cp.async stage A (hi+lo) and B(block 0) ---
    {
        const char* aH = (const char*)(g_Ah + (size_t)(rbase + s_row) * NHID);
        const char* aL = (const char*)(g_Al + (size_t)(rbase + s_row) * NHID);
        #pragma unroll
        for (int q = 0; q < 4; q++) {
            const int qq = s_q * 4 + q;
            cp16(smB + OFF_AH + (s_row * LDA + qq * 8) * 2, aH + qq * 16);
            cp16(smB + OFF_AL + (s_row * LDA + qq * 8) * 2, aL + qq * 16);
        }
        const int cc0 = blockIdx.x * 64;   // block 0 for this CTA column
        const char* bH = (const char*)(g_Bh + (size_t)(cc0 + s_row) * NHID);
        const char* bL = (const char*)(g_Bl + (size_t)(cc0 + s_row) * NHID);
        #pragma unroll
        for (int q = 0; q < 4; q++) {
            const int qq = s_q * 4 + q;
            cp16(smB + OFF_BH + (s_row * LDA + qq * 8) * 2, bH + qq * 16);
            cp16(smB + OFF_BL + (s_row * LDA + qq * 8) * 2, bL + qq * 16);
        }
        cp_commit();
    }

    // warp tiling: 2 row-groups x 4 col-groups
    const int wr = (wid & 1)  * 32;        // 0 or 32
    const int wc = (wid >> 1) * 16;        // 0,16,32,48

    const int g8 = lid & 7, q4 = lid >> 3;
    const int a_row  = g8 + ((q4 & 1) << 3);
    const int a_koff = (q4 >> 1) << 3;
    const int b_row  = g8 + ((q4 >> 1) << 3);
    const int b_koff = (q4 & 1) << 3;

    uint32_t aAddrH[2], aAddrL[2];
    #pragma unroll
    for (int mi = 0; mi < 2; mi++) {
        const uint32_t off = ((wr + mi * 16 + a_row) * LDA + a_koff) * 2;
        aAddrH[mi] = smB + OFF_AH + off;
        aAddrL[mi] = smB + OFF_AL + off;
    }
    const uint32_t bOffs = ((wc + b_row) * LDA + b_koff) * 2;
    const uint32_t bAddrH = smB + OFF_BH + bOffs;
    const uint32_t bAddrL = smB + OFF_BL + bOffs;

    const int g = lid >> 2, tg = lid & 3;

    for (int bi = 0; bi < 8; bi++) {
        const int blk = bi * CTAX + blockIdx.x;
        if (blk >= NBLK) break;
        const int cb = blk * 32;

        cp_wait0();
        __syncthreads();                   // staged data visible to all

        // prefetch per-thread cluster biases (2 ni values)
        float2 bp[2];
        #pragma unroll
        for (int ni = 0; ni < 2; ni++) {
            int cl = cb + ((wc + ni * 8) >> 1) + tg;
            bp[ni] = g_b2p[cl < NCLUST ? cl : (NCLUST - 1)];
        }

        // --- MMA ---
        float acc[2][2][4];
        #pragma unroll
        for (int mi = 0; mi < 2; mi++)
            #pragma unroll
            for (int ni = 0; ni < 2; ni++)
                #pragma unroll
                for (int r = 0; r < 4; r++) acc[mi][ni][r] = 0.0f;

        #pragma unroll
        for (int ks = 0; ks < 8; ks++) {
            const uint32_t kb = ks * 32;
            uint32_t ah[2][4], al[2][4], bh[2][2], bl[2][2];
            #pragma unroll
            for (int mi = 0; mi < 2; mi++) {
                ldsm_x4(ah[mi][0], ah[mi][1], ah[mi][2], ah[mi][3], aAddrH[mi] + kb);
                ldsm_x4(al[mi][0], al[mi][1], al[mi][2], al[mi][3], aAddrL[mi] + kb);
            }
            ldsm_x4(bh[0][0], bh[0][1], bh[1][0], bh[1][1], bAddrH + kb);
            ldsm_x4(bl[0][0], bl[0][1], bl[1][0], bl[1][1], bAddrL + kb);

            #pragma unroll
            for (int mi = 0; mi < 2; mi++)
                #pragma unroll
                for (int ni = 0; ni < 2; ni++)
                    mma16816(acc[mi][ni], ah[mi], bh[ni]);
            #pragma unroll
            for (int mi = 0; mi < 2; mi++)
                #pragma unroll
                for (int ni = 0; ni < 2; ni++)
                    mma16816(acc[mi][ni], ah[mi], bl[ni]);
            #pragma unroll
            for (int mi = 0; mi < 2; mi++)
                #pragma unroll
                for (int ni = 0; ni < 2; ni++)
                    mma16816(acc[mi][ni], al[mi], bh[ni]);
        }
        __syncthreads();                   // B fully consumed -> Cbuf may overwrite

        // --- epilogue STS: softmax into Cbuf (row = actual local row) ---
        #pragma unroll
        for (int mi = 0; mi < 2; mi++) {
            const int r0 = wr + mi * 16 + g;
            #pragma unroll
            for (int ni = 0; ni < 2; ni++) {
                const int cl_loc = ((wc + ni * 8) >> 1) + tg;
                if (cb + cl_loc < NCLUST) {
                    float e1 = fexp(acc[mi][ni][0] + bp[ni].x);
                    float e2 = fexp(acc[mi][ni][1] + bp[ni].y);
                    float inv = frcp(1.0f + e1 + e2);
                    float* d = Cbuf + r0 * LDCB + 3 * cl_loc;
                    d[0] = inv; d[1] = e1 * inv; d[2] = e2 * inv;
                    e1 = fexp(acc[mi][ni][2] + bp[ni].x);
                    e2 = fexp(acc[mi][ni][3] + bp[ni].y);
                    inv = frcp(1.0f + e1 + e2);
                    d = Cbuf + (r0 + 8) * LDCB + 3 * cl_loc;
                    d[0] = inv; d[1] = e1 * inv; d[2] = e2 * inv;
                }
            }
        }
        __syncthreads();

        // --- copy-out: dense STG.128 ---
        const int vcl = (cb + 32 <= NCLUST) ? 32 : (NCLUST - cb);
        if (vcl == 32) {
            #pragma unroll
            for (int i = tid; i < 64 * 24; i += 256) {
                const int lr = i / 24, q = i - lr * 24;
                float4 val = *(float4*)(Cbuf + lr * LDCB + q * 4);
                *(float4*)(out + (size_t)(rbase + lr) * NOUT + 3 * cb + q * 4) = val;
            }
        } else {
            for (int i = tid; i < 64 * 12; i += 256) {
                const int lr = i / 12, q = i - lr * 12;
                float4 val = *(float4*)(Cbuf + lr * LDCB + q * 4);
                *(float4*)(out + (size_t)(rbase + lr) * NOUT + 3 * cb + q * 4) = val;
            }
        }

        // --- stage next B (overwrites Cbuf region; gated by barrier) ---
        const int nblk = (bi + 1) * CTAX + blockIdx.x;
        if (nblk < NBLK) {
            __syncthreads();               // copy-out done reading Cbuf
            const int cc0 = nblk * 64;
            const char* bH = (const char*)(g_Bh + (size_t)(cc0 + s_row) * NHID);
            const char* bL = (const char*)(g_Bl + (size_t)(cc0 + s_row) * NHID);
            #pragma unroll
            for (int q = 0; q < 4; q++) {
                const int qq = s_q * 4 + q;
                cp16(smB + OFF_BH + (s_row * LDA + qq * 8) * 2, bH + qq * 16);
                cp16(smB + OFF_BL + (s_row * LDA + qq * 8) * 2, bL + qq * 16);
            }
            cp_commit();
        }
    }
}

// ---------------------------------------------------------------------------
extern "C" void kernel_launch(void* const* d_in, const int* in_sizes, int n_in,
                              void* d_out, int out_size) {
    const float* z     = (const float*)d_in[0];
    const float* W1    = (const float*)d_in[1];
    const float* b1    = (const float*)d_in[2];
    const float* gamma = (const float*)d_in[3];
    const float* beta  = (const float*)d_in[4];
    const float* W2    = (const float*)d_in[5];
    const float* b2    = (const float*)d_in[6];
    float* out = (float*)d_out;

    k_init<<<1, 128>>>();
    k_h<<<BATCH / 128, 256>>>(z, W1, b1);
    k_bn<<<1, 128>>>(gamma, beta);
    k_split_h<<<(BATCH * NHID + 255) / 256, 256>>>();
    k_split_w<<<(NCC_PAD * NHID + 255) / 256, 256>>>(W2, b2);

    cudaFuncSetAttribute(k_gemm, cudaFuncAttributeMaxDynamicSharedMemorySize,
                         SMEM_DYN);
    dim3 grid(CTAX, BATCH / 64);   // (40, 64) = 2560 CTAs
    k_gemm<<<grid, 256, SMEM_DYN>>>(out);
}

// round 11
// speedup vs baseline: 1.1365x; 1.1365x over previous
#include <cuda_runtime.h>
#include <cuda_bf16.h>
#include <math.h>
#include <cstdint>

#define BATCH  4096
#define NIN    32
#define NHID   128
#define NOUT   30000
#define NCLUST 10000
#define BN_EPS 1e-3f

#define NCC      20000
#define NCC_PAD  20480
#define NBLK     313
#define CTAX     37            // 37*32 = 1184 CTAs = exactly 4 waves @ occ 2

// ---- scratch ----
__device__ float g_h[BATCH * NHID];
__device__ float g_sum[NHID];
__device__ float g_sumsq[NHID];
__device__ float g_scale[NHID];
__device__ float g_shift[NHID];
__device__ __nv_bfloat16 g_Ah[BATCH * NHID];
__device__ __nv_bfloat16 g_Al[BATCH * NHID];
__device__ __nv_bfloat16 g_Bh[NCC_PAD * NHID];
__device__ __nv_bfloat16 g_Bl[NCC_PAD * NHID];
__device__ float2 g_b2p[10240];

// ---- MUFU-free exp / rcp ----------------------------------------------------
__device__ __forceinline__ float fexp(float x) {
    float t  = x * 1.4426950408889634f;
    float rf = t + 12582912.0f;
    int   ri = __float_as_int(rf) - 0x4B400000;
    float f  = t - (rf - 12582912.0f);
    float p = 1.3333558e-3f;               // deg-5: dropped f^6 term (<2.4e-6)
    p = fmaf(p, f, 9.6181291e-3f);
    p = fmaf(p, f, 5.5504109e-2f);
    p = fmaf(p, f, 2.4022651e-1f);
    p = fmaf(p, f, 6.9314718e-1f);
    p = fmaf(p, f, 1.0f);
    return __int_as_float(__float_as_int(p) + (ri << 23));
}
__device__ __forceinline__ float frcp(float d) {
    float r = __int_as_float(0x7EF127EAu - __float_as_int(d));
    #pragma unroll
    for (int i = 0; i < 2; i++) {          // (3.4%)^4 ~ 1.3e-6
        float e = fmaf(-d, r, 1.0f);
        r = fmaf(r, e, r);
    }
    return r;
}

__device__ __forceinline__ uint32_t smem_u32(const void* p) {
    uint32_t a;
    asm("{ .reg .u64 t; cvta.to.shared.u64 t, %1; cvt.u32.u64 %0, t; }"
        : "=r"(a) : "l"(p));
    return a;
}
__device__ __forceinline__ void cp16(uint32_t dst, const void* src) {
    asm volatile("cp.async.cg.shared.global [%0], [%1], 16;"
                 :: "r"(dst), "l"(src));
}
__device__ __forceinline__ void cp_commit() {
    asm volatile("cp.async.commit_group;");
}
__device__ __forceinline__ void cp_wait0() {
    asm volatile("cp.async.wait_group 0;");
}
__device__ __forceinline__ void ldsm_x4(uint32_t& r0, uint32_t& r1,
                                        uint32_t& r2, uint32_t& r3, uint32_t a) {
    asm volatile("ldmatrix.sync.aligned.m8n8.x4.shared.b16 {%0,%1,%2,%3}, [%4];"
                 : "=r"(r0), "=r"(r1), "=r"(r2), "=r"(r3) : "r"(a));
}
__device__ __forceinline__ void mma16816(float* c, const uint32_t* a,
                                         const uint32_t* b) {
    asm volatile("mma.sync.aligned.m16n8k16.row.col.f32.bf16.bf16.f32 "
                 "{%0,%1,%2,%3}, {%4,%5,%6,%7}, {%8,%9}, {%0,%1,%2,%3};"
                 : "+f"(c[0]), "+f"(c[1]), "+f"(c[2]), "+f"(c[3])
                 : "r"(a[0]), "r"(a[1]), "r"(a[2]), "r"(a[3]),
                   "r"(b[0]), "r"(b[1]));
}

// ---------------------------------------------------------------------------
__global__ void k_init() {
    int i = threadIdx.x;
    if (i < NHID) { g_sum[i] = 0.0f; g_sumsq[i] = 0.0f; }
}

__global__ void k_h(const float* __restrict__ z,
                    const float* __restrict__ W1,
                    const float* __restrict__ b1) {
    __shared__ float zs[128][33];
    __shared__ float ws[128][33];
    __shared__ float ps[2][128];
    __shared__ float psq[2][128];

    const int tid   = threadIdx.x;
    const int rbase = blockIdx.x * 128;

    for (int idx = tid; idx < 128 * NIN; idx += 256) {
        int r = idx >> 5, k = idx & 31;
        zs[r][k] = z[(rbase + r) * NIN + k];
        ws[r][k] = W1[idx];
    }
    __syncthreads();

    const int col = tid & 127;
    const int rh  = tid >> 7;
    const float bb = b1[col];
    float ls = 0.0f, lsq = 0.0f;

    for (int r = rh * 64; r < rh * 64 + 64; r++) {
        float acc = bb;
        #pragma unroll
        for (int k = 0; k < NIN; k++)
            acc = fmaf(zs[r][k], ws[col][k], acc);
        g_h[(rbase + r) * NHID + col] = acc;
        ls += acc;
        lsq = fmaf(acc, acc, lsq);
    }
    ps[rh][col]  = ls;
    psq[rh][col] = lsq;
    __syncthreads();
    if (tid < 128) {
        atomicAdd(&g_sum[tid],   ps[0][tid]  + ps[1][tid]);
        atomicAdd(&g_sumsq[tid], psq[0][tid] + psq[1][tid]);
    }
}

__global__ void k_bn(const float* __restrict__ gamma,
                     const float* __restrict__ beta) {
    int c = threadIdx.x;
    if (c >= NHID) return;
    const float inv_b = 1.0f / (float)BATCH;
    float mu   = g_sum[c] * inv_b;
    float var  = g_sumsq[c] * inv_b - mu * mu;
    float rstd = rsqrtf(var + BN_EPS);
    float sc   = gamma[c] * rstd;
    g_scale[c] = sc;
    g_shift[c] = beta[c] - mu * sc;
}

__global__ void k_split_h() {
    const int idx = blockIdx.x * 256 + threadIdx.x;
    if (idx >= BATCH * NHID) return;
    const int k = idx & 127;
    float v = fmaxf(fmaf(g_h[idx], g_scale[k], g_shift[k]), 0.0f);
    __nv_bfloat16 hi = __float2bfloat16_rn(v);
    g_Ah[idx] = hi;
    g_Al[idx] = __float2bfloat16_rn(v - __bfloat162float(hi));
}

__global__ void k_split_w(const float* __restrict__ W2,
                          const float* __restrict__ b2) {
    const int idx = blockIdx.x * 256 + threadIdx.x;
    if (idx < 10240) {
        float2 bp = make_float2(0.0f, 0.0f);
        if (idx < NCLUST)
            bp = make_float2(b2[3 * idx + 1], b2[3 * idx + 2]);
        g_b2p[idx] = bp;
    }
    if (idx >= NCC_PAD * NHID) return;
    const int cc = idx >> 7;
    const int k  = idx & 127;
    float w = 0.0f;
    if (cc < NCC) {
        const int c = cc >> 1, j = cc & 1;
        w = W2[(size_t)(3 * c + 1 + j) * NHID + k];
    }
    __nv_bfloat16 hi = __float2bfloat16_rn(w);
    g_Bh[idx] = hi;
    g_Bl[idx] = __float2bfloat16_rn(w - __bfloat162float(hi));
}

// ---------------------------------------------------------------------------
// k_gemm: 128x64 A-resident mma.sync GEMM + staged coalesced softmax output.
// cp.async staging; exactly 4 waves at occupancy 2.
// ---------------------------------------------------------------------------
#define LDA 136
#define LDCB 100

#define OFF_AH 0
#define OFF_AL 34816
#define OFF_BH 69632
#define OFF_BL 87040
#define SMEM_DYN 104448        // Cbuf [64][100] f32 = 25600 B overlays B region

extern "C" __global__ void __launch_bounds__(256, 2)
k_gemm(float* __restrict__ out) {
    extern __shared__ char sm[];
    float* Cbuf = (float*)(sm + OFF_BH);

    const int tid   = threadIdx.x;
    const int wid   = tid >> 5;
    const int lid   = tid & 31;
    const int rbase = blockIdx.y * 128;

    const uint32_t smB = smem_u32(sm);

    // B-staging slot: 64 rows x 16 quads, 4 quads/thread
    const int sb_row = tid >> 2;
    const int sb_q   = (tid & 3) * 4;

    // --- prologue: cp.async stage A (hi+lo, 8 quads/thread each) + B(blk0) ---
    {
        const int sa_row = tid >> 1;          // 0..127
        const int sa_q   = (tid & 1) * 8;     // 0 or 8
        const char* aH = (const char*)(g_Ah + (size_t)(rbase + sa_row) * NHID);
        const char* aL = (const char*)(g_Al + (size_t)(rbase + sa_row) * NHID);
        #pragma unroll
        for (int q = 0; q < 8; q++) {
            const int qq = sa_q + q;
            cp16(smB + OFF_AH + (sa_row * LDA + qq * 8) * 2, aH + qq * 16);
            cp16(smB + OFF_AL + (sa_row * LDA + qq * 8) * 2, aL + qq * 16);
        }
        const int cc0 = blockIdx.x * 64;
        const char* bH = (const char*)(g_Bh + (size_t)(cc0 + sb_row) * NHID);
        const char* bL = (const char*)(g_Bl + (size_t)(cc0 + sb_row) * NHID);
        #pragma unroll
        for (int q = 0; q < 4; q++) {
            const int qq = sb_q + q;
            cp16(smB + OFF_BH + (sb_row * LDA + qq * 8) * 2, bH + qq * 16);
            cp16(smB + OFF_BL + (sb_row * LDA + qq * 8) * 2, bL + qq * 16);
        }
        cp_commit();
    }

    const int wr = (wid >> 1) * 32;
    const int wc = (wid & 1)  * 32;

    const int g8 = lid & 7, q4 = lid >> 3;
    const int a_row  = g8 + ((q4 & 1) << 3);
    const int a_koff = (q4 >> 1) << 3;
    const int b_row  = g8 + ((q4 >> 1) << 3);
    const int b_koff = (q4 & 1) << 3;

    uint32_t aAddrH[2], aAddrL[2];
    #pragma unroll
    for (int mi = 0; mi < 2; mi++) {
        const uint32_t off = ((wr + mi * 16 + a_row) * LDA + a_koff) * 2;
        aAddrH[mi] = smB + OFF_AH + off;
        aAddrL[mi] = smB + OFF_AL + off;
    }
    uint32_t bAddrH[2], bAddrL[2];
    #pragma unroll
    for (int np = 0; np < 2; np++) {
        const uint32_t off = ((wc + np * 16 + b_row) * LDA + b_koff) * 2;
        bAddrH[np] = smB + OFF_BH + off;
        bAddrL[np] = smB + OFF_BL + off;
    }

    const int g = lid >> 2, tg = lid & 3;
    const int lrow0 = (wr >> 1) + g;

    for (int bi = 0; bi < 9; bi++) {
        const int blk = bi * CTAX + blockIdx.x;
        if (blk >= NBLK) break;
        const int cb = blk * 32;

        cp_wait0();
        __syncthreads();                 // staged A(+B) visible

        // prefetch biases for this thread's 4 clusters
        float2 bp[4];
        #pragma unroll
        for (int ni = 0; ni < 4; ni++) {
            int cl = cb + ((wc + ni * 8) >> 1) + tg;
            bp[ni] = g_b2p[cl < NCLUST ? cl : (NCLUST - 1)];
        }

        // --- MMA: acc[mi][ni][4], chain-major over 8 independent accs ---
        float acc[2][4][4];
        #pragma unroll
        for (int mi = 0; mi < 2; mi++)
            #pragma unroll
            for (int ni = 0; ni < 4; ni++)
                #pragma unroll
                for (int r = 0; r < 4; r++) acc[mi][ni][r] = 0.0f;

        #pragma unroll
        for (int ks = 0; ks < 8; ks++) {
            const uint32_t kb = ks * 32;
            uint32_t ah[2][4], al[2][4], bh[4][2], bl[4][2];
            #pragma unroll
            for (int mi = 0; mi < 2; mi++) {
                ldsm_x4(ah[mi][0], ah[mi][1], ah[mi][2], ah[mi][3], aAddrH[mi] + kb);
                ldsm_x4(al[mi][0], al[mi][1], al[mi][2], al[mi][3], aAddrL[mi] + kb);
            }
            #pragma unroll
            for (int np = 0; np < 2; np++) {
                ldsm_x4(bh[2*np][0], bh[2*np][1], bh[2*np+1][0], bh[2*np+1][1],
                        bAddrH[np] + kb);
                ldsm_x4(bl[2*np][0], bl[2*np][1], bl[2*np+1][0], bl[2*np+1][1],
                        bAddrL[np] + kb);
            }
            #pragma unroll
            for (int mi = 0; mi < 2; mi++)
                #pragma unroll
                for (int ni = 0; ni < 4; ni++)
                    mma16816(acc[mi][ni], ah[mi], bh[ni]);
            #pragma unroll
            for (int mi = 0; mi < 2; mi++)
                #pragma unroll
                for (int ni = 0; ni < 4; ni++)
                    mma16816(acc[mi][ni], ah[mi], bl[ni]);
            #pragma unroll
            for (int mi = 0; mi < 2; mi++)
                #pragma unroll
                for (int ni = 0; ni < 4; ni++)
                    mma16816(acc[mi][ni], al[mi], bh[ni]);
        }
        __syncthreads();                 // B consumed -> Cbuf may overwrite

        // --- epilogue: 2 row-passes, staged + coalesced __stcs stores ---
        const int vcl = (cb + 32 <= NCLUST) ? 32 : (NCLUST - cb);

        #pragma unroll
        for (int pass = 0; pass < 2; pass++) {
            #pragma unroll
            for (int ni = 0; ni < 4; ni++) {
                const int cl_loc = ((wc + ni * 8) >> 1) + tg;
                if (cb + cl_loc < NCLUST) {
                    float e1 = fexp(acc[pass][ni][0] + bp[ni].x);
                    float e2 = fexp(acc[pass][ni][1] + bp[ni].y);
                    float inv = frcp(1.0f + e1 + e2);
                    float* d = Cbuf + lrow0 * LDCB + 3 * cl_loc;
                    d[0] = inv; d[1] = e1 * inv; d[2] = e2 * inv;
                    e1 = fexp(acc[pass][ni][2] + bp[ni].x);
                    e2 = fexp(acc[pass][ni][3] + bp[ni].y);
                    inv = frcp(1.0f + e1 + e2);
                    d = Cbuf + (lrow0 + 8) * LDCB + 3 * cl_loc;
                    d[0] = inv; d[1] = e1 * inv; d[2] = e2 * inv;
                }
            }
            __syncthreads();

            if (vcl == 32) {
                #pragma unroll
                for (int i = tid; i < 64 * 24; i += 256) {
                    const int lr = i / 24, q = i - lr * 24;
                    const int grow = rbase + ((lr >> 4) << 5) + (pass << 4) + (lr & 15);
                    float4 val = *(float4*)(Cbuf + lr * LDCB + q * 4);
                    __stcs((float4*)(out + (size_t)grow * NOUT + 3 * cb + q * 4), val);
                }
            } else {
                for (int i = tid; i < 64 * 12; i += 256) {
                    const int lr = i / 12, q = i - lr * 12;
                    const int grow = rbase + ((lr >> 4) << 5) + (pass << 4) + (lr & 15);
                    float4 val = *(float4*)(Cbuf + lr * LDCB + q * 4);
                    __stcs((float4*)(out + (size_t)grow * NOUT + 3 * cb + q * 4), val);
                }
            }
            __syncthreads();
        }

        // --- stage next B via cp.async (Cbuf region free after last sync) ---
        const int nblk = (bi + 1) * CTAX + blockIdx.x;
        if (nblk < NBLK) {
            const int cc0 = nblk * 64;
            const char* bH = (const char*)(g_Bh + (size_t)(cc0 + sb_row) * NHID);
            const char* bL = (const char*)(g_Bl + (size_t)(cc0 + sb_row) * NHID);
            #pragma unroll
            for (int q = 0; q < 4; q++) {
                const int qq = sb_q + q;
                cp16(smB + OFF_BH + (sb_row * LDA + qq * 8) * 2, bH + qq * 16);
                cp16(smB + OFF_BL + (sb_row * LDA + qq * 8) * 2, bL + qq * 16);
            }
            cp_commit();
        }
    }
}

// ---------------------------------------------------------------------------
extern "C" void kernel_launch(void* const* d_in, const int* in_sizes, int n_in,
                              void* d_out, int out_size) {
    const float* z     = (const float*)d_in[0];
    const float* W1    = (const float*)d_in[1];
    const float* b1    = (const float*)d_in[2];
    const float* gamma = (const float*)d_in[3];
    const float* beta  = (const float*)d_in[4];
    const float* W2    = (const float*)d_in[5];
    const float* b2    = (const float*)d_in[6];
    float* out = (float*)d_out;

    k_init<<<1, 128>>>();
    k_h<<<BATCH / 128, 256>>>(z, W1, b1);
    k_bn<<<1, 128>>>(gamma, beta);
    k_split_h<<<(BATCH * NHID + 255) / 256, 256>>>();
    k_split_w<<<(NCC_PAD * NHID + 255) / 256, 256>>>(W2, b2);

    cudaFuncSetAttribute(k_gemm, cudaFuncAttributeMaxDynamicSharedMemorySize,
                         SMEM_DYN);
    dim3 grid(CTAX, BATCH / 128);   // (37, 32) = 1184 CTAs = 4 waves
    k_gemm<<<grid, 256, SMEM_DYN>>>(out);
}

// round 12
// speedup vs baseline: 1.1477x; 1.0098x over previous
#include <cuda_runtime.h>
#include <cuda_bf16.h>
#include <math.h>
#include <cstdint>

#define BATCH  4096
#define NIN    32
#define NHID   128
#define NOUT   30000
#define NCLUST 10000
#define BN_EPS 1e-3f

#define NCC      20000
#define NCC_PAD  20480
#define NBLK     313
#define CTAX     37            // 37*32 = 1184 CTAs = exactly 4 waves @ occ 2

// ---- scratch ----
__device__ float g_h[BATCH * NHID];
__device__ float g_sum[NHID];
__device__ float g_sumsq[NHID];
__device__ float g_scale[NHID];
__device__ float g_shift[NHID];
__device__ __nv_bfloat16 g_Ah[BATCH * NHID];
__device__ __nv_bfloat16 g_Al[BATCH * NHID];
__device__ __nv_bfloat16 g_Bh[NCC_PAD * NHID];
__device__ __nv_bfloat16 g_Bl[NCC_PAD * NHID];
__device__ float2 g_b2p[10240];

// ---- MUFU-free exp / rcp ----------------------------------------------------
__device__ __forceinline__ float fexp(float x) {
    float t  = x * 1.4426950408889634f;
    float rf = t + 12582912.0f;
    int   ri = __float_as_int(rf) - 0x4B400000;
    float f  = t - (rf - 12582912.0f);
    float p = 1.3333558e-3f;
    p = fmaf(p, f, 9.6181291e-3f);
    p = fmaf(p, f, 5.5504109e-2f);
    p = fmaf(p, f, 2.4022651e-1f);
    p = fmaf(p, f, 6.9314718e-1f);
    p = fmaf(p, f, 1.0f);
    return __int_as_float(__float_as_int(p) + (ri << 23));
}
__device__ __forceinline__ float frcp(float d) {
    float r = __int_as_float(0x7EF127EAu - __float_as_int(d));
    #pragma unroll
    for (int i = 0; i < 2; i++) {
        float e = fmaf(-d, r, 1.0f);
        r = fmaf(r, e, r);
    }
    return r;
}

__device__ __forceinline__ uint32_t smem_u32(const void* p) {
    uint32_t a;
    asm("{ .reg .u64 t; cvta.to.shared.u64 t, %1; cvt.u32.u64 %0, t; }"
        : "=r"(a) : "l"(p));
    return a;
}
__device__ __forceinline__ void cp16(uint32_t dst, const void* src) {
    asm volatile("cp.async.cg.shared.global [%0], [%1], 16;"
                 :: "r"(dst), "l"(src));
}
__device__ __forceinline__ void cp_commit() {
    asm volatile("cp.async.commit_group;");
}
__device__ __forceinline__ void cp_wait0() {
    asm volatile("cp.async.wait_group 0;");
}
__device__ __forceinline__ void ldsm_x4(uint32_t& r0, uint32_t& r1,
                                        uint32_t& r2, uint32_t& r3, uint32_t a) {
    asm volatile("ldmatrix.sync.aligned.m8n8.x4.shared.b16 {%0,%1,%2,%3}, [%4];"
                 : "=r"(r0), "=r"(r1), "=r"(r2), "=r"(r3) : "r"(a));
}
__device__ __forceinline__ void mma16816(float* c, const uint32_t* a,
                                         const uint32_t* b) {
    asm volatile("mma.sync.aligned.m16n8k16.row.col.f32.bf16.bf16.f32 "
                 "{%0,%1,%2,%3}, {%4,%5,%6,%7}, {%8,%9}, {%0,%1,%2,%3};"
                 : "+f"(c[0]), "+f"(c[1]), "+f"(c[2]), "+f"(c[3])
                 : "r"(a[0]), "r"(a[1]), "r"(a[2]), "r"(a[3]),
                   "r"(b[0]), "r"(b[1]));
}

// ---------------------------------------------------------------------------
__global__ void k_init() {
    int i = threadIdx.x;
    if (i < NHID) { g_sum[i] = 0.0f; g_sumsq[i] = 0.0f; }
}

__global__ void k_h(const float* __restrict__ z,
                    const float* __restrict__ W1,
                    const float* __restrict__ b1) {
    __shared__ float zs[128][33];
    __shared__ float ws[128][33];
    __shared__ float ps[2][128];
    __shared__ float psq[2][128];

    const int tid   = threadIdx.x;
    const int rbase = blockIdx.x * 128;

    for (int idx = tid; idx < 128 * NIN; idx += 256) {
        int r = idx >> 5, k = idx & 31;
        zs[r][k] = z[(rbase + r) * NIN + k];
        ws[r][k] = W1[idx];
    }
    __syncthreads();

    const int col = tid & 127;
    const int rh  = tid >> 7;
    const float bb = b1[col];
    float ls = 0.0f, lsq = 0.0f;

    for (int r = rh * 64; r < rh * 64 + 64; r++) {
        float acc = bb;
        #pragma unroll
        for (int k = 0; k < NIN; k++)
            acc = fmaf(zs[r][k], ws[col][k], acc);
        g_h[(rbase + r) * NHID + col] = acc;
        ls += acc;
        lsq = fmaf(acc, acc, lsq);
    }
    ps[rh][col]  = ls;
    psq[rh][col] = lsq;
    __syncthreads();
    if (tid < 128) {
        atomicAdd(&g_sum[tid],   ps[0][tid]  + ps[1][tid]);
        atomicAdd(&g_sumsq[tid], psq[0][tid] + psq[1][tid]);
    }
}

__global__ void k_bn(const float* __restrict__ gamma,
                     const float* __restrict__ beta) {
    int c = threadIdx.x;
    if (c >= NHID) return;
    const float inv_b = 1.0f / (float)BATCH;
    float mu   = g_sum[c] * inv_b;
    float var  = g_sumsq[c] * inv_b - mu * mu;
    float rstd = rsqrtf(var + BN_EPS);
    float sc   = gamma[c] * rstd;
    g_scale[c] = sc;
    g_shift[c] = beta[c] - mu * sc;
}

__global__ void k_split_h() {
    const int idx = blockIdx.x * 256 + threadIdx.x;
    if (idx >= BATCH * NHID) return;
    const int k = idx & 127;
    float v = fmaxf(fmaf(g_h[idx], g_scale[k], g_shift[k]), 0.0f);
    __nv_bfloat16 hi = __float2bfloat16_rn(v);
    g_Ah[idx] = hi;
    g_Al[idx] = __float2bfloat16_rn(v - __bfloat162float(hi));
}

__global__ void k_split_w(const float* __restrict__ W2,
                          const float* __restrict__ b2) {
    const int idx = blockIdx.x * 256 + threadIdx.x;
    if (idx < 10240) {
        float2 bp = make_float2(0.0f, 0.0f);
        if (idx < NCLUST)
            bp = make_float2(b2[3 * idx + 1], b2[3 * idx + 2]);
        g_b2p[idx] = bp;
    }
    if (idx >= NCC_PAD * NHID) return;
    const int cc = idx >> 7;
    const int k  = idx & 127;
    float w = 0.0f;
    if (cc < NCC) {
        const int c = cc >> 1, j = cc & 1;
        w = W2[(size_t)(3 * c + 1 + j) * NHID + k];
    }
    __nv_bfloat16 hi = __float2bfloat16_rn(w);
    g_Bh[idx] = hi;
    g_Bl[idx] = __float2bfloat16_rn(w - __bfloat162float(hi));
}

// ---------------------------------------------------------------------------
// k_gemm: 128x64 A-resident mma.sync GEMM; next-B register-prefetch hidden
// behind MMA+epilogue; staged coalesced softmax output; 4 exact waves.
// ---------------------------------------------------------------------------
#define LDA 136
#define LDCB 100

#define OFF_AH 0
#define OFF_AL 34816
#define OFF_BH 69632
#define OFF_BL 87040
#define SMEM_DYN 104448        // Cbuf [64][100] f32 = 25600 B overlays B region

extern "C" __global__ void __launch_bounds__(256, 2)
k_gemm(float* __restrict__ out) {
    extern __shared__ char sm[];
    float* Cbuf = (float*)(sm + OFF_BH);

    const int tid   = threadIdx.x;
    const int wid   = tid >> 5;
    const int lid   = tid & 31;
    const int rbase = blockIdx.y * 128;

    const uint32_t smB = smem_u32(sm);

    // B-staging slot: 64 rows x 16 quads per array, 4 quads/thread
    const int sb_row = tid >> 2;
    const int sb_q   = (tid & 3) * 4;
    const uint32_t bStsH = smB + OFF_BH + (sb_row * LDA + sb_q * 8) * 2;
    const uint32_t bStsL = smB + OFF_BL + (sb_row * LDA + sb_q * 8) * 2;

    // --- prologue: cp.async stage A (hi+lo) + B(blk 0) ---
    {
        const int sa_row = tid >> 1;
        const int sa_q   = (tid & 1) * 8;
        const char* aH = (const char*)(g_Ah + (size_t)(rbase + sa_row) * NHID);
        const char* aL = (const char*)(g_Al + (size_t)(rbase + sa_row) * NHID);
        #pragma unroll
        for (int q = 0; q < 8; q++) {
            const int qq = sa_q + q;
            cp16(smB + OFF_AH + (sa_row * LDA + qq * 8) * 2, aH + qq * 16);
            cp16(smB + OFF_AL + (sa_row * LDA + qq * 8) * 2, aL + qq * 16);
        }
        const int cc0 = blockIdx.x * 64;
        const uint4* bH = (const uint4*)(g_Bh + (size_t)(cc0 + sb_row) * NHID);
        const uint4* bL = (const uint4*)(g_Bl + (size_t)(cc0 + sb_row) * NHID);
        #pragma unroll
        for (int q = 0; q < 4; q++) {
            cp16(bStsH + q * 16, bH + sb_q + q);
            cp16(bStsL + q * 16, bL + sb_q + q);
        }
        cp_commit();
    }

    const int wr = (wid >> 1) * 32;
    const int wc = (wid & 1)  * 32;

    const int g8 = lid & 7, q4 = lid >> 3;
    const int a_row  = g8 + ((q4 & 1) << 3);
    const int a_koff = (q4 >> 1) << 3;
    const int b_row  = g8 + ((q4 >> 1) << 3);
    const int b_koff = (q4 & 1) << 3;

    uint32_t aAddrH[2], aAddrL[2];
    #pragma unroll
    for (int mi = 0; mi < 2; mi++) {
        const uint32_t off = ((wr + mi * 16 + a_row) * LDA + a_koff) * 2;
        aAddrH[mi] = smB + OFF_AH + off;
        aAddrL[mi] = smB + OFF_AL + off;
    }
    uint32_t bAddrH[2], bAddrL[2];
    #pragma unroll
    for (int np = 0; np < 2; np++) {
        const uint32_t off = ((wc + np * 16 + b_row) * LDA + b_koff) * 2;
        bAddrH[np] = smB + OFF_BH + off;
        bAddrL[np] = smB + OFF_BL + off;
    }

    const int g = lid >> 2, tg = lid & 3;
    const int lrow0 = (wr >> 1) + g;

    cp_wait0();                          // prologue staging complete

    for (int bi = 0; bi < 9; bi++) {
        const int blk = bi * CTAX + blockIdx.x;
        if (blk >= NBLK) break;
        const int cb = blk * 32;

        __syncthreads();                 // staged B visible (prologue or STS)

        // --- register-prefetch NEXT block's B (latency hidden by MMA+epi) ---
        const int nblk = (bi + 1) * CTAX + blockIdx.x;
        const int pcc0 = (nblk < NBLK ? nblk : 0) * 64;
        uint4 pfh[4], pfl[4];
        {
            const uint4* bH = (const uint4*)(g_Bh + (size_t)(pcc0 + sb_row) * NHID);
            const uint4* bL = (const uint4*)(g_Bl + (size_t)(pcc0 + sb_row) * NHID);
            #pragma unroll
            for (int q = 0; q < 4; q++) {
                pfh[q] = __ldg(bH + sb_q + q);
                pfl[q] = __ldg(bL + sb_q + q);
            }
        }

        // prefetch biases for this thread's 4 clusters
        float2 bp[4];
        #pragma unroll
        for (int ni = 0; ni < 4; ni++) {
            int cl = cb + ((wc + ni * 8) >> 1) + tg;
            bp[ni] = g_b2p[cl < NCLUST ? cl : (NCLUST - 1)];
        }

        // --- MMA: acc[mi][ni][4], chain-major over 8 independent accs ---
        float acc[2][4][4];
        #pragma unroll
        for (int mi = 0; mi < 2; mi++)
            #pragma unroll
            for (int ni = 0; ni < 4; ni++)
                #pragma unroll
                for (int r = 0; r < 4; r++) acc[mi][ni][r] = 0.0f;

        #pragma unroll
        for (int ks = 0; ks < 8; ks++) {
            const uint32_t kb = ks * 32;
            uint32_t ah[2][4], al[2][4], bh[4][2], bl[4][2];
            #pragma unroll
            for (int mi = 0; mi < 2; mi++) {
                ldsm_x4(ah[mi][0], ah[mi][1], ah[mi][2], ah[mi][3], aAddrH[mi] + kb);
                ldsm_x4(al[mi][0], al[mi][1], al[mi][2], al[mi][3], aAddrL[mi] + kb);
            }
            #pragma unroll
            for (int np = 0; np < 2; np++) {
                ldsm_x4(bh[2*np][0], bh[2*np][1], bh[2*np+1][0], bh[2*np+1][1],
                        bAddrH[np] + kb);
                ldsm_x4(bl[2*np][0], bl[2*np][1], bl[2*np+1][0], bl[2*np+1][1],
                        bAddrL[np] + kb);
            }
            #pragma unroll
            for (int mi = 0; mi < 2; mi++)
                #pragma unroll
                for (int ni = 0; ni < 4; ni++)
                    mma16816(acc[mi][ni], ah[mi], bh[ni]);
            #pragma unroll
            for (int mi = 0; mi < 2; mi++)
                #pragma unroll
                for (int ni = 0; ni < 4; ni++)
                    mma16816(acc[mi][ni], ah[mi], bl[ni]);
            #pragma unroll
            for (int mi = 0; mi < 2; mi++)
                #pragma unroll
                for (int ni = 0; ni < 4; ni++)
                    mma16816(acc[mi][ni], al[mi], bh[ni]);
        }
        __syncthreads();                 // B consumed -> Cbuf may overwrite

        // --- epilogue: 2 row-passes, staged + coalesced __stcs stores ---
        const int vcl = (cb + 32 <= NCLUST) ? 32 : (NCLUST - cb);

        #pragma unroll
        for (int pass = 0; pass < 2; pass++) {
            #pragma unroll
            for (int ni = 0; ni < 4; ni++) {
                const int cl_loc = ((wc + ni * 8) >> 1) + tg;
                if (cb + cl_loc < NCLUST) {
                    float e1 = fexp(acc[pass][ni][0] + bp[ni].x);
                    float e2 = fexp(acc[pass][ni][1] + bp[ni].y);
                    float inv = frcp(1.0f + e1 + e2);
                    float* d = Cbuf + lrow0 * LDCB + 3 * cl_loc;
                    d[0] = inv; d[1] = e1 * inv; d[2] = e2 * inv;
                    e1 = fexp(acc[pass][ni][2] + bp[ni].x);
                    e2 = fexp(acc[pass][ni][3] + bp[ni].y);
                    inv = frcp(1.0f + e1 + e2);
                    d = Cbuf + (lrow0 + 8) * LDCB + 3 * cl_loc;
                    d[0] = inv; d[1] = e1 * inv; d[2] = e2 * inv;
                }
            }
            __syncthreads();

            if (vcl == 32) {
                #pragma unroll
                for (int i = tid; i < 64 * 24; i += 256) {
                    const int lr = i / 24, q = i - lr * 24;
                    const int grow = rbase + ((lr >> 4) << 5) + (pass << 4) + (lr & 15);
                    float4 val = *(float4*)(Cbuf + lr * LDCB + q * 4);
                    __stcs((float4*)(out + (size_t)grow * NOUT + 3 * cb + q * 4), val);
                }
            } else {
                for (int i = tid; i < 64 * 12; i += 256) {
                    const int lr = i / 12, q = i - lr * 12;
                    const int grow = rbase + ((lr >> 4) << 5) + (pass << 4) + (lr & 15);
                    float4 val = *(float4*)(Cbuf + lr * LDCB + q * 4);
                    __stcs((float4*)(out + (size_t)grow * NOUT + 3 * cb + q * 4), val);
                }
            }
            __syncthreads();
        }

        // --- STS prefetched next-B into (now free) B region ---
        if (nblk < NBLK) {
            #pragma unroll
            for (int q = 0; q < 4; q++) {
                *(uint4*)(sm + (bStsH - smB) + q * 16) = pfh[q];
                *(uint4*)(sm + (bStsL - smB) + q * 16) = pfl[q];
            }
        }
    }
}

// ---------------------------------------------------------------------------
extern "C" void kernel_launch(void* const* d_in, const int* in_sizes, int n_in,
                              void* d_out, int out_size) {
    const float* z     = (const float*)d_in[0];
    const float* W1    = (const float*)d_in[1];
    const float* b1    = (const float*)d_in[2];
    const float* gamma = (const float*)d_in[3];
    const float* beta  = (const float*)d_in[4];
    const float* W2    = (const float*)d_in[5];
    const float* b2    = (const float*)d_in[6];
    float* out = (float*)d_out;

    k_init<<<1, 128>>>();
    k_h<<<BATCH / 128, 256>>>(z, W1, b1);
    k_bn<<<1, 128>>>(gamma, beta);
    k_split_h<<<(BATCH * NHID + 255) / 256, 256>>>();
    k_split_w<<<(NCC_PAD * NHID + 255) / 256, 256>>>(W2, b2);

    cudaFuncSetAttribute(k_gemm, cudaFuncAttributeMaxDynamicSharedMemorySize,
                         SMEM_DYN);
    dim3 grid(CTAX, BATCH / 128);   // (37, 32) = 1184 CTAs = 4 waves
    k_gemm<<<grid, 256, SMEM_DYN>>>(out);
}